// round 1
// baseline (speedup 1.0000x reference)
#include <cuda_runtime.h>
#include <cstdint>

#define SEQ 4096
#define BATCH 4
#define DM 1024
#define NH 16
#define HD 64
#define MTOT (SEQ*BATCH)     // 16384
#define NCH 16
#define RPC (SEQ/NCH)        // 256 rows per chunk
#define NPAIR (BATCH*NH)     // 64

// ---------------- scratch (device globals; no allocations allowed) ----------
__device__ float g_Qp [(size_t)NPAIR*SEQ*HD];   // [B,H,S,d]
__device__ float g_Kp [(size_t)NPAIR*SEQ*HD];
__device__ float g_V  [(size_t)NPAIR*SEQ*HD];
__device__ float g_attn[(size_t)MTOT*DM];       // [S,B,D]
__device__ float g_pKV[(size_t)NPAIR*NCH*HD*HD];
__device__ float g_pKs[(size_t)NPAIR*NCH*HD];
__device__ float g_KV [(size_t)NPAIR*HD*HD];
__device__ float g_Ks [(size_t)NPAIR*HD];

// ---------------- tf32 GEMM: C[M,N] = A[M,K] * W[N,K]^T + bias --------------
#define BM 128
#define BN 128
#define BK 16
#define KST 20   // BK + 4 pad -> fragment LDS banks (4*gid + tig) all distinct

__device__ __forceinline__ void cp16(void* dst, const void* src){
  uint32_t s = (uint32_t)__cvta_generic_to_shared(dst);
  asm volatile("cp.async.ca.shared.global [%0], [%1], 16;\n" :: "r"(s), "l"(src));
}
__device__ __forceinline__ uint32_t f2tf(float v){
  uint32_t r; asm("cvt.rna.tf32.f32 %0, %1;" : "=r"(r) : "f"(v)); return r;
}

// MODE 0: out[row*DM+col] (standard [S,B,D] row-major)
// MODE 1: out[((b*NH+h)*SEQ+s)*HD+dd]  with row=s*BATCH+b, col=h*64+dd
// ACT  1: elu(x)+1  (x>0 ? x+1 : exp(x))
template<int MODE, int ACT>
__global__ __launch_bounds__(256,2) void gemm_tn(
    const float* __restrict__ A, const float* __restrict__ W,
    const float* __restrict__ bias, float* __restrict__ out, int Kd)
{
  __shared__ float sA[2][BM][KST];
  __shared__ float sB[2][BN][KST];
  const int tid  = threadIdx.x;
  const int lane = tid & 31, warp = tid >> 5;
  const int gid  = lane >> 2, tig = lane & 3;
  const int wm   = warp >> 2, wn  = warp & 3;     // 2 x 4 warp grid, 64x32 per warp
  const int m0   = blockIdx.y * BM, n0 = blockIdx.x * BN;

  float acc[4][4][4];
  #pragma unroll
  for (int i=0;i<4;i++)
    #pragma unroll
    for (int j=0;j<4;j++)
      #pragma unroll
      for (int k=0;k<4;k++) acc[i][j][k]=0.f;

  const int KT = Kd / BK;

  // per tile: 128 rows x 4 float4 = 512 f4 each for A and B; 2 per thread each
  #define ISSUE(buf, kt) do {                                             \
    _Pragma("unroll")                                                     \
    for (int i=0;i<2;i++){                                                \
      int f4 = tid + i*256;                                               \
      int r = f4 >> 2, c = (f4 & 3)*4;                                    \
      cp16(&sA[buf][r][c], A + (size_t)(m0+r)*Kd + (kt)*BK + c);          \
      cp16(&sB[buf][r][c], W + (size_t)(n0+r)*Kd + (kt)*BK + c);          \
    }                                                                     \
    asm volatile("cp.async.commit_group;\n");                             \
  } while(0)

  ISSUE(0, 0);
  for (int t=0; t<KT; t++){
    asm volatile("cp.async.wait_group 0;\n");
    __syncthreads();
    if (t+1 < KT) { int nb=(t+1)&1; ISSUE(nb, t+1); }
    const int buf = t & 1;
    #pragma unroll
    for (int ks=0; ks<BK/8; ks++){
      uint32_t af[4][4], bf[4][2];
      #pragma unroll
      for (int im=0; im<4; im++){
        int r = wm*64 + im*16 + gid;
        af[im][0] = f2tf(sA[buf][r  ][ks*8+tig  ]);
        af[im][1] = f2tf(sA[buf][r+8][ks*8+tig  ]);
        af[im][2] = f2tf(sA[buf][r  ][ks*8+tig+4]);
        af[im][3] = f2tf(sA[buf][r+8][ks*8+tig+4]);
      }
      #pragma unroll
      for (int jn=0; jn<4; jn++){
        int c = wn*32 + jn*8 + gid;
        bf[jn][0] = f2tf(sB[buf][c][ks*8+tig  ]);
        bf[jn][1] = f2tf(sB[buf][c][ks*8+tig+4]);
      }
      #pragma unroll
      for (int im=0; im<4; im++)
        #pragma unroll
        for (int jn=0; jn<4; jn++){
          asm volatile(
            "mma.sync.aligned.m16n8k8.row.col.f32.tf32.tf32.f32 "
            "{%0,%1,%2,%3}, {%4,%5,%6,%7}, {%8,%9}, {%0,%1,%2,%3};\n"
            : "+f"(acc[im][jn][0]), "+f"(acc[im][jn][1]),
              "+f"(acc[im][jn][2]), "+f"(acc[im][jn][3])
            : "r"(af[im][0]), "r"(af[im][1]), "r"(af[im][2]), "r"(af[im][3]),
              "r"(bf[jn][0]), "r"(bf[jn][1]));
        }
    }
    __syncthreads();
  }
  #undef ISSUE

  // epilogue: c0:(g,2t) c1:(g,2t+1) c2:(g+8,2t) c3:(g+8,2t+1)
  #pragma unroll
  for (int im=0; im<4; im++){
    #pragma unroll
    for (int jn=0; jn<4; jn++){
      int row0 = m0 + wm*64 + im*16 + gid;
      int col0 = n0 + wn*32 + jn*8 + tig*2;
      #pragma unroll
      for (int k=0;k<4;k++){
        int row = row0 + ((k>=2) ? 8 : 0);
        int col = col0 + (k&1);
        float v = acc[im][jn][k] + bias[col];
        if (ACT) v = (v > 0.f) ? (v + 1.f) : __expf(v);
        if (MODE == 0){
          out[(size_t)row*DM + col] = v;
        } else {
          int s = row >> 2, b = row & 3;      // row = s*BATCH + b, BATCH=4
          int hh = col >> 6, dd = col & 63;
          out[(((size_t)(b*NH + hh))*SEQ + s)*HD + dd] = v;
        }
      }
    }
  }
}

// ---------------- KV partial: per (pair, chunk): KV_p = Kp^T V over 256 rows -
__global__ __launch_bounds__(256) void kv_partial(
    const float* __restrict__ Kp, const float* __restrict__ V,
    float* __restrict__ pKV, float* __restrict__ pKs)
{
  const int p  = blockIdx.x;   // b*16+h
  const int ch = blockIdx.y;   // 0..NCH-1
  __shared__ float sK[64][64];
  __shared__ float sV[64][64];
  const int tid = threadIdx.x;
  const int ti = tid >> 4, tj = tid & 15;    // 16x16 thread grid, 4x4 outputs each

  float acc[4][4];
  #pragma unroll
  for (int i=0;i<4;i++)
    #pragma unroll
    for (int j=0;j<4;j++) acc[i][j]=0.f;
  float ksum = 0.f;

  const float* Kbase = Kp + ((size_t)p*SEQ + (size_t)ch*RPC)*HD;
  const float* Vbase = V  + ((size_t)p*SEQ + (size_t)ch*RPC)*HD;

  for (int tile=0; tile<RPC/64; tile++){
    #pragma unroll
    for (int i=0;i<4;i++){
      int idx = tid + i*256;   // 1024 float4 = 64x64 floats
      ((float4*)&sK[0][0])[idx] = ((const float4*)(Kbase + (size_t)tile*64*HD))[idx];
      ((float4*)&sV[0][0])[idx] = ((const float4*)(Vbase + (size_t)tile*64*HD))[idx];
    }
    __syncthreads();
    #pragma unroll 4
    for (int s=0; s<64; s++){
      float4 a = *(const float4*)&sK[s][ti*4];
      float4 b = *(const float4*)&sV[s][tj*4];
      acc[0][0]+=a.x*b.x; acc[0][1]+=a.x*b.y; acc[0][2]+=a.x*b.z; acc[0][3]+=a.x*b.w;
      acc[1][0]+=a.y*b.x; acc[1][1]+=a.y*b.y; acc[1][2]+=a.y*b.z; acc[1][3]+=a.y*b.w;
      acc[2][0]+=a.z*b.x; acc[2][1]+=a.z*b.y; acc[2][2]+=a.z*b.z; acc[2][3]+=a.z*b.w;
      acc[3][0]+=a.w*b.x; acc[3][1]+=a.w*b.y; acc[3][2]+=a.w*b.z; acc[3][3]+=a.w*b.w;
    }
    if (tid < 64){
      #pragma unroll 8
      for (int s=0;s<64;s++) ksum += sK[s][tid];
    }
    __syncthreads();
  }

  float* dst = pKV + ((size_t)p*NCH + ch)*HD*HD;
  #pragma unroll
  for (int i=0;i<4;i++)
    #pragma unroll
    for (int j=0;j<4;j++)
      dst[(ti*4+i)*HD + tj*4+j] = acc[i][j];
  if (tid < 64) pKs[((size_t)p*NCH + ch)*HD + tid] = ksum;
}

__global__ void kv_reduce(const float* __restrict__ pKV, const float* __restrict__ pKs,
                          float* __restrict__ KV, float* __restrict__ Ks)
{
  const int p = blockIdx.x;
  for (int i=threadIdx.x; i<HD*HD; i+=blockDim.x){
    float s=0.f;
    #pragma unroll
    for (int c=0;c<NCH;c++) s += pKV[((size_t)p*NCH+c)*HD*HD + i];
    KV[(size_t)p*HD*HD + i] = s;
  }
  if (threadIdx.x < HD){
    float s=0.f;
    #pragma unroll
    for (int c=0;c<NCH;c++) s += pKs[((size_t)p*NCH+c)*HD + threadIdx.x];
    Ks[(size_t)p*HD + threadIdx.x] = s;
  }
}

// ---------------- out_attn = (Qp . KV) / (Qp . Ksum + 1e-6) ------------------
__global__ __launch_bounds__(256) void attn_apply(
    const float* __restrict__ Qp, const float* __restrict__ KV,
    const float* __restrict__ Ks, float* __restrict__ attn)
{
  const int p  = blockIdx.x;      // b*16+h
  const int st = blockIdx.y;      // tile of 128 rows
  __shared__ float sKV[64][64];
  __shared__ float sKs[64];
  const int tid=threadIdx.x, warp=tid>>5, lane=tid&31;

  for (int i=tid;i<HD*HD/4;i+=256)
    ((float4*)&sKV[0][0])[i] = ((const float4*)(KV + (size_t)p*HD*HD))[i];
  if (tid<HD) sKs[tid] = Ks[(size_t)p*HD + tid];
  __syncthreads();

  const int b = p >> 4, hh = p & 15;
  for (int r=warp; r<128; r+=8){
    int s = st*128 + r;
    float2 q2 = *(const float2*)(Qp + ((size_t)p*SEQ + s)*HD + 2*lane);
    float z = q2.x*sKs[2*lane] + q2.y*sKs[2*lane+1];
    #pragma unroll
    for (int off=16; off; off>>=1) z += __shfl_xor_sync(0xffffffffu, z, off);
    z += 1e-6f;
    float a0=0.f, a1=0.f;
    #pragma unroll
    for (int d=0; d<64; d++){
      float qd = __shfl_sync(0xffffffffu, (d&1)?q2.y:q2.x, d>>1);
      float2 kvv = *(const float2*)&sKV[d][2*lane];
      a0 += qd*kvv.x; a1 += qd*kvv.y;
    }
    float inv = 1.0f / z;
    float2 o; o.x = a0*inv; o.y = a1*inv;
    *(float2*)(attn + ((size_t)s*BATCH + b)*DM + hh*HD + 2*lane) = o;
  }
}

// ---------------- host ------------------------------------------------------
extern "C" void kernel_launch(void* const* d_in, const int* in_sizes, int n_in,
                              void* d_out, int out_size)
{
  const float* h  = (const float*)d_in[0];
  const float* x  = (const float*)d_in[1];
  const float* Wq = (const float*)d_in[2];
  const float* bq = (const float*)d_in[3];
  const float* Wk = (const float*)d_in[4];
  const float* bk = (const float*)d_in[5];
  const float* Wv = (const float*)d_in[6];
  const float* bv = (const float*)d_in[7];
  const float* Wo = (const float*)d_in[8];
  const float* bo = (const float*)d_in[9];

  float *qp,*kp,*vv,*attn,*pkv,*pks,*kv,*ks;
  cudaGetSymbolAddress((void**)&qp,   g_Qp);
  cudaGetSymbolAddress((void**)&kp,   g_Kp);
  cudaGetSymbolAddress((void**)&vv,   g_V);
  cudaGetSymbolAddress((void**)&attn, g_attn);
  cudaGetSymbolAddress((void**)&pkv,  g_pKV);
  cudaGetSymbolAddress((void**)&pks,  g_pKs);
  cudaGetSymbolAddress((void**)&kv,   g_KV);
  cudaGetSymbolAddress((void**)&ks,   g_Ks);

  dim3 gg(DM/BN, MTOT/BM);   // 8 x 128
  gemm_tn<1,1><<<gg,256>>>(h, Wq, bq, qp, DM);
  gemm_tn<1,1><<<gg,256>>>(x, Wk, bk, kp, DM);
  gemm_tn<1,0><<<gg,256>>>(x, Wv, bv, vv, DM);
  kv_partial<<<dim3(NPAIR, NCH),256>>>(kp, vv, pkv, pks);
  kv_reduce<<<NPAIR,256>>>(pkv, pks, kv, ks);
  attn_apply<<<dim3(NPAIR, SEQ/128),256>>>(qp, kv, ks, attn);
  gemm_tn<0,0><<<gg,256>>>(attn, Wo, bo, (float*)d_out, DM);
}

// round 5
// speedup vs baseline: 1.0990x; 1.0990x over previous
#include <cuda_runtime.h>
#include <cstdint>

#define SEQ 4096
#define BATCH 4
#define DM 1024
#define NH 16
#define HD 64
#define MTOT (SEQ*BATCH)     // 16384
#define NPAIR (BATCH*NH)     // 64
#define NCH 16
#define RPC (SEQ/NCH)        // 256
#define ROWST ((size_t)BATCH*DM)   // 4096 floats between consecutive s

// GEMM tiling: 128x128 CTA tile, 4 warps of 64x64, BK=16, 2-stage cp.async
#define BM 128
#define BN 128
#define BK 16
#define KST 20   // BK + 4 pad (R1-proven layout)

// ---------------- scratch (device globals) ----------------------------------
__device__ float g_Qp [(size_t)MTOT*DM];   // row-major [s*4+b, h*64+d]
__device__ float g_Kp [(size_t)MTOT*DM];
__device__ float g_V  [(size_t)MTOT*DM];
__device__ float g_attn[(size_t)MTOT*DM];
__device__ float g_pKV[(size_t)NPAIR*NCH*HD*HD];
__device__ float g_pKs[(size_t)NPAIR*NCH*HD];
__device__ float g_KV [(size_t)NPAIR*HD*HD];
__device__ float g_Ks [(size_t)NPAIR*HD];

// ---------------- helpers ----------------------------------------------------
__device__ __forceinline__ void cp16(void* dst, const void* src){
  uint32_t s = (uint32_t)__cvta_generic_to_shared(dst);
  asm volatile("cp.async.ca.shared.global [%0], [%1], 16;\n" :: "r"(s), "l"(src));
}
__device__ __forceinline__ uint32_t f2tf(float v){
  uint32_t r; asm("cvt.rna.tf32.f32 %0, %1;" : "=r"(r) : "f"(v)); return r;
}

// ---------------- tf32 GEMM: C[M,N] = A[M,K] * W[N,K]^T + bias (+elu+1) ------
template<int ACT>
__global__ __launch_bounds__(128,2) void gemm_ts(
    const float* __restrict__ A, const float* __restrict__ W,
    const float* __restrict__ bias, float* __restrict__ out)
{
  __shared__ float sA[2][BM][KST];
  __shared__ float sB[2][BN][KST];
  const int tid  = threadIdx.x;
  const int lane = tid & 31, warp = tid >> 5;
  const int gid  = lane >> 2, tig = lane & 3;
  const int wm   = warp >> 1, wn  = warp & 1;       // 2x2 warps, 64x64 each
  const int m0   = blockIdx.y * BM, n0 = blockIdx.x * BN;

  float acc[4][8][4];
  #pragma unroll
  for (int i=0;i<4;i++)
    #pragma unroll
    for (int j=0;j<8;j++)
      #pragma unroll
      for (int k=0;k<4;k++) acc[i][j][k]=0.f;

  const int KT = DM / BK;   // 64

  // per stage: A and B each 128 rows x 4 float4; 4 per thread each
  #define ISSUE(buf, kt) do {                                             \
    _Pragma("unroll")                                                     \
    for (int j = 0; j < 4; j++){                                          \
      int f4 = tid + j*128;                                               \
      int r = f4 >> 2, c = (f4 & 3)*4;                                    \
      cp16(&sA[buf][r][c], A + (size_t)(m0+r)*DM + (kt)*BK + c);          \
      cp16(&sB[buf][r][c], W + (size_t)(n0+r)*DM + (kt)*BK + c);          \
    }                                                                     \
    asm volatile("cp.async.commit_group;\n");                             \
  } while(0)

  ISSUE(0, 0);
  for (int t = 0; t < KT; t++){
    asm volatile("cp.async.wait_group 0;\n");
    __syncthreads();
    if (t+1 < KT) { int nb=(t+1)&1; ISSUE(nb, t+1); }
    const int buf = t & 1;
    #pragma unroll
    for (int ks = 0; ks < BK/8; ks++){
      uint32_t af[4][4], bf[8][2];
      #pragma unroll
      for (int im = 0; im < 4; im++){
        int r = wm*64 + im*16 + gid;
        af[im][0] = f2tf(sA[buf][r  ][ks*8+tig  ]);
        af[im][1] = f2tf(sA[buf][r+8][ks*8+tig  ]);
        af[im][2] = f2tf(sA[buf][r  ][ks*8+tig+4]);
        af[im][3] = f2tf(sA[buf][r+8][ks*8+tig+4]);
      }
      #pragma unroll
      for (int jn = 0; jn < 8; jn++){
        int c = wn*64 + jn*8 + gid;
        bf[jn][0] = f2tf(sB[buf][c][ks*8+tig  ]);
        bf[jn][1] = f2tf(sB[buf][c][ks*8+tig+4]);
      }
      #pragma unroll
      for (int im = 0; im < 4; im++)
        #pragma unroll
        for (int jn = 0; jn < 8; jn++){
          asm volatile(
            "mma.sync.aligned.m16n8k8.row.col.f32.tf32.tf32.f32 "
            "{%0,%1,%2,%3}, {%4,%5,%6,%7}, {%8,%9}, {%0,%1,%2,%3};\n"
            : "+f"(acc[im][jn][0]), "+f"(acc[im][jn][1]),
              "+f"(acc[im][jn][2]), "+f"(acc[im][jn][3])
            : "r"(af[im][0]), "r"(af[im][1]), "r"(af[im][2]), "r"(af[im][3]),
              "r"(bf[jn][0]), "r"(bf[jn][1]));
        }
    }
    __syncthreads();
  }
  #undef ISSUE

  // epilogue: c0:(g,2t) c1:(g,2t+1) c2:(g+8,2t) c3:(g+8,2t+1)
  #pragma unroll
  for (int im = 0; im < 4; im++){
    int row = m0 + wm*64 + im*16 + gid;
    #pragma unroll
    for (int jn = 0; jn < 8; jn++){
      int col = n0 + wn*64 + jn*8 + tig*2;
      float b0 = bias[col], b1 = bias[col+1];
      float v0 = acc[im][jn][0] + b0;
      float v1 = acc[im][jn][1] + b1;
      float v2 = acc[im][jn][2] + b0;
      float v3 = acc[im][jn][3] + b1;
      if (ACT){
        v0 = (v0 > 0.f) ? (v0 + 1.f) : __expf(v0);
        v1 = (v1 > 0.f) ? (v1 + 1.f) : __expf(v1);
        v2 = (v2 > 0.f) ? (v2 + 1.f) : __expf(v2);
        v3 = (v3 > 0.f) ? (v3 + 1.f) : __expf(v3);
      }
      float2 o0; o0.x = v0; o0.y = v1;
      float2 o1; o1.x = v2; o1.y = v3;
      *(float2*)(out + (size_t)row*DM + col)     = o0;
      *(float2*)(out + (size_t)(row+8)*DM + col) = o1;
    }
  }
}

// ---------------- KV partial: per (pair, chunk): KV_p = Kp^T V ---------------
__global__ __launch_bounds__(256) void kv_partial(
    const float* __restrict__ Kp, const float* __restrict__ V,
    float* __restrict__ pKV, float* __restrict__ pKs)
{
  const int p  = blockIdx.x;   // b*16+h
  const int ch = blockIdx.y;
  const int b = p >> 4, hh = p & 15;
  __shared__ float sK[64][64];
  __shared__ float sV[64][64];
  const int tid = threadIdx.x;
  const int ti = tid >> 4, tj = tid & 15;

  float acc[4][4];
  #pragma unroll
  for (int i=0;i<4;i++)
    #pragma unroll
    for (int j=0;j<4;j++) acc[i][j]=0.f;
  float ksum = 0.f;

  const float* Kb = Kp + ((size_t)(ch*RPC)*BATCH + b)*DM + hh*HD;
  const float* Vb = V  + ((size_t)(ch*RPC)*BATCH + b)*DM + hh*HD;

  for (int tile = 0; tile < RPC/64; tile++){
    #pragma unroll
    for (int i = 0; i < 4; i++){
      int idx = tid + i*256;          // 1024 float4
      int r = idx >> 4, c4 = idx & 15;
      size_t src = (size_t)(tile*64 + r)*ROWST + c4*4;
      ((float4*)&sK[0][0])[idx] = *(const float4*)(Kb + src);
      ((float4*)&sV[0][0])[idx] = *(const float4*)(Vb + src);
    }
    __syncthreads();
    #pragma unroll 4
    for (int s = 0; s < 64; s++){
      float4 a = *(const float4*)&sK[s][ti*4];
      float4 c = *(const float4*)&sV[s][tj*4];
      acc[0][0]+=a.x*c.x; acc[0][1]+=a.x*c.y; acc[0][2]+=a.x*c.z; acc[0][3]+=a.x*c.w;
      acc[1][0]+=a.y*c.x; acc[1][1]+=a.y*c.y; acc[1][2]+=a.y*c.z; acc[1][3]+=a.y*c.w;
      acc[2][0]+=a.z*c.x; acc[2][1]+=a.z*c.y; acc[2][2]+=a.z*c.z; acc[2][3]+=a.z*c.w;
      acc[3][0]+=a.w*c.x; acc[3][1]+=a.w*c.y; acc[3][2]+=a.w*c.z; acc[3][3]+=a.w*c.w;
    }
    if (tid < 64){
      #pragma unroll 8
      for (int s=0;s<64;s++) ksum += sK[s][tid];
    }
    __syncthreads();
  }

  float* dst = pKV + ((size_t)p*NCH + ch)*HD*HD;
  #pragma unroll
  for (int i=0;i<4;i++)
    #pragma unroll
    for (int j=0;j<4;j++)
      dst[(ti*4+i)*HD + tj*4+j] = acc[i][j];
  if (tid < 64) pKs[((size_t)p*NCH + ch)*HD + tid] = ksum;
}

__global__ void kv_reduce(const float* __restrict__ pKV, const float* __restrict__ pKs,
                          float* __restrict__ KV, float* __restrict__ Ks)
{
  const int p = blockIdx.x;
  for (int i = threadIdx.x; i < HD*HD; i += blockDim.x){
    float s = 0.f;
    #pragma unroll
    for (int c = 0; c < NCH; c++) s += pKV[((size_t)p*NCH+c)*HD*HD + i];
    KV[(size_t)p*HD*HD + i] = s;
  }
  if (threadIdx.x < HD){
    float s = 0.f;
    #pragma unroll
    for (int c = 0; c < NCH; c++) s += pKs[((size_t)p*NCH+c)*HD + threadIdx.x];
    Ks[(size_t)p*HD + threadIdx.x] = s;
  }
}

// ---------------- attn = (Qp . KV) / (Qp . Ksum + 1e-6) ----------------------
__global__ __launch_bounds__(256) void attn_apply(
    const float* __restrict__ Qp, const float* __restrict__ KV,
    const float* __restrict__ Ks, float* __restrict__ attn)
{
  const int p  = blockIdx.x;
  const int st = blockIdx.y;
  __shared__ float sKV[64][64];
  __shared__ float sKs[64];
  const int tid = threadIdx.x, warp = tid >> 5, lane = tid & 31;

  for (int i = tid; i < HD*HD/4; i += 256)
    ((float4*)&sKV[0][0])[i] = ((const float4*)(KV + (size_t)p*HD*HD))[i];
  if (tid < HD) sKs[tid] = Ks[(size_t)p*HD + tid];
  __syncthreads();

  const int b = p >> 4, hh = p & 15;
  for (int r = warp; r < 128; r += 8){
    int s = st*128 + r;
    size_t base = ((size_t)s*BATCH + b)*DM + hh*HD;
    float2 q2 = *(const float2*)(Qp + base + 2*lane);
    float z = q2.x*sKs[2*lane] + q2.y*sKs[2*lane+1];
    #pragma unroll
    for (int off = 16; off; off >>= 1) z += __shfl_xor_sync(0xffffffffu, z, off);
    z += 1e-6f;
    float a0 = 0.f, a1 = 0.f;
    #pragma unroll
    for (int d = 0; d < 64; d++){
      float qd = __shfl_sync(0xffffffffu, (d&1) ? q2.y : q2.x, d>>1);
      float2 kvv = *(const float2*)&sKV[d][2*lane];
      a0 += qd*kvv.x; a1 += qd*kvv.y;
    }
    float inv = 1.0f / z;
    float2 o; o.x = a0*inv; o.y = a1*inv;
    *(float2*)(attn + base + 2*lane) = o;
  }
}

// ---------------- host ------------------------------------------------------
extern "C" void kernel_launch(void* const* d_in, const int* in_sizes, int n_in,
                              void* d_out, int out_size)
{
  const float* h  = (const float*)d_in[0];
  const float* x  = (const float*)d_in[1];
  const float* Wq = (const float*)d_in[2];
  const float* bq = (const float*)d_in[3];
  const float* Wk = (const float*)d_in[4];
  const float* bk = (const float*)d_in[5];
  const float* Wv = (const float*)d_in[6];
  const float* bv = (const float*)d_in[7];
  const float* Wo = (const float*)d_in[8];
  const float* bo = (const float*)d_in[9];

  float *qp,*kp,*vv,*attn,*pkv,*pks,*kv,*ks;
  cudaGetSymbolAddress((void**)&qp,   g_Qp);
  cudaGetSymbolAddress((void**)&kp,   g_Kp);
  cudaGetSymbolAddress((void**)&vv,   g_V);
  cudaGetSymbolAddress((void**)&attn, g_attn);
  cudaGetSymbolAddress((void**)&pkv,  g_pKV);
  cudaGetSymbolAddress((void**)&pks,  g_pKs);
  cudaGetSymbolAddress((void**)&kv,   g_KV);
  cudaGetSymbolAddress((void**)&ks,   g_Ks);

  dim3 gg(DM/BN, MTOT/BM);   // 8 x 128
  gemm_ts<1><<<gg, 128>>>(h, Wq, bq, qp);
  gemm_ts<1><<<gg, 128>>>(x, Wk, bk, kp);
  gemm_ts<0><<<gg, 128>>>(x, Wv, bv, vv);

  kv_partial<<<dim3(NPAIR, NCH), 256>>>(kp, vv, pkv, pks);
  kv_reduce<<<NPAIR, 256>>>(pkv, pks, kv, ks);
  attn_apply<<<dim3(NPAIR, SEQ/128), 256>>>(qp, kv, ks, attn);

  gemm_ts<0><<<gg, 128>>>(attn, Wo, bo, (float*)d_out);
}

// round 8
// speedup vs baseline: 1.1046x; 1.0051x over previous
#include <cuda_runtime.h>
#include <cstdint>

#define SEQ 4096
#define BATCH 4
#define DM 1024
#define NH 16
#define HD 64
#define MTOT (SEQ*BATCH)     // 16384
#define NPAIR (BATCH*NH)     // 64
#define NCH 16
#define RPC (SEQ/NCH)        // 256

// GEMM tiling: 128x128 CTA tile, 4 warps of 64x64, BK=16, 2-stage padded smem
#define BM 128
#define BN 128
#define BK 16
#define KST 20   // BK + 4 pad (R1/R5-proven layout, 40 KB total)

// ---------------- scratch (device globals) ----------------------------------
__device__ float g_Qp [(size_t)MTOT*DM];   // [B,H,S,d]
__device__ float g_Kp [(size_t)MTOT*DM];
__device__ float g_V  [(size_t)MTOT*DM];
__device__ float g_attn[(size_t)MTOT*DM];  // row-major [s*4+b, D]
__device__ float g_pKV[(size_t)NPAIR*NCH*HD*HD];
__device__ float g_pKs[(size_t)NPAIR*NCH*HD];
__device__ float g_KV [(size_t)NPAIR*HD*HD];
__device__ float g_Ks [(size_t)NPAIR*HD];

// ---------------- helpers ----------------------------------------------------
__device__ __forceinline__ void cp16(void* dst, const void* src){
  uint32_t s = (uint32_t)__cvta_generic_to_shared(dst);
  asm volatile("cp.async.ca.shared.global [%0], [%1], 16;\n" :: "r"(s), "l"(src));
}
__device__ __forceinline__ uint32_t f2tf(float v){
  uint32_t r; asm("cvt.rna.tf32.f32 %0, %1;" : "=r"(r) : "f"(v)); return r;
}

// ---------------- tf32 GEMM: C[M,N] = A[M,K] * W[N,K]^T + bias (+elu+1) ------
// MODE 0: out[row*DM+col] row-major.  MODE 1: out[((b*NH+h)*SEQ+s)*HD+dd],
//         row = s*BATCH+b, col = h*64+dd.  (R1-proven mapping)
template<int MODE, int ACT>
__global__ __launch_bounds__(128,2) void gemm_ts(
    const float* __restrict__ A, const float* __restrict__ W,
    const float* __restrict__ bias, float* __restrict__ out)
{
  __shared__ float sA[2][BM][KST];
  __shared__ float sB[2][BN][KST];
  const int tid  = threadIdx.x;
  const int lane = tid & 31, warp = tid >> 5;
  const int gid  = lane >> 2, tig = lane & 3;
  const int wm   = warp >> 1, wn  = warp & 1;       // 2x2 warps, 64x64 each
  const int m0   = blockIdx.y * BM, n0 = blockIdx.x * BN;

  float acc[4][8][4];
  #pragma unroll
  for (int i=0;i<4;i++)
    #pragma unroll
    for (int j=0;j<8;j++)
      #pragma unroll
      for (int k=0;k<4;k++) acc[i][j][k]=0.f;

  const int KT = DM / BK;   // 64

  // per stage: A and B each 128 rows x 4 float4; 4 per thread each
  #define ISSUE(buf, kt) do {                                             \
    _Pragma("unroll")                                                     \
    for (int j = 0; j < 4; j++){                                          \
      int f4 = tid + j*128;                                               \
      int r = f4 >> 2, c = (f4 & 3)*4;                                    \
      cp16(&sA[buf][r][c], A + (size_t)(m0+r)*DM + (kt)*BK + c);          \
      cp16(&sB[buf][r][c], W + (size_t)(n0+r)*DM + (kt)*BK + c);          \
    }                                                                     \
    asm volatile("cp.async.commit_group;\n" ::: "memory");                \
  } while(0)

  ISSUE(0, 0);
  ISSUE(1, 1);
  for (int t = 0; t < KT; t++){
    // outstanding groups here: {t, t+1} (t+1 only if it was issued)
    if (t + 1 < KT) asm volatile("cp.async.wait_group 1;\n" ::: "memory");
    else            asm volatile("cp.async.wait_group 0;\n" ::: "memory");
    __syncthreads();
    const int buf = t & 1;
    #pragma unroll
    for (int ks = 0; ks < BK/8; ks++){
      uint32_t af[4][4], bf[8][2];
      #pragma unroll
      for (int im = 0; im < 4; im++){
        int r = wm*64 + im*16 + gid;
        af[im][0] = f2tf(sA[buf][r  ][ks*8+tig  ]);
        af[im][1] = f2tf(sA[buf][r+8][ks*8+tig  ]);
        af[im][2] = f2tf(sA[buf][r  ][ks*8+tig+4]);
        af[im][3] = f2tf(sA[buf][r+8][ks*8+tig+4]);
      }
      #pragma unroll
      for (int jn = 0; jn < 8; jn++){
        int c = wn*64 + jn*8 + gid;
        bf[jn][0] = f2tf(sB[buf][c][ks*8+tig  ]);
        bf[jn][1] = f2tf(sB[buf][c][ks*8+tig+4]);
      }
      #pragma unroll
      for (int im = 0; im < 4; im++)
        #pragma unroll
        for (int jn = 0; jn < 8; jn++){
          asm volatile(
            "mma.sync.aligned.m16n8k8.row.col.f32.tf32.tf32.f32 "
            "{%0,%1,%2,%3}, {%4,%5,%6,%7}, {%8,%9}, {%0,%1,%2,%3};\n"
            : "+f"(acc[im][jn][0]), "+f"(acc[im][jn][1]),
              "+f"(acc[im][jn][2]), "+f"(acc[im][jn][3])
            : "r"(af[im][0]), "r"(af[im][1]), "r"(af[im][2]), "r"(af[im][3]),
              "r"(bf[jn][0]), "r"(bf[jn][1]));
        }
    }
    __syncthreads();
    // overwrite stage t&1 (just finished computing on it) with k-step t+2
    if (t + 2 < KT) ISSUE(buf, t+2);
  }
  #undef ISSUE

  // epilogue: c0:(g,2t) c1:(g,2t+1) c2:(g+8,2t) c3:(g+8,2t+1)
  #pragma unroll
  for (int im = 0; im < 4; im++){
    int row0 = m0 + wm*64 + im*16 + gid;
    #pragma unroll
    for (int jn = 0; jn < 8; jn++){
      int col = n0 + wn*64 + jn*8 + tig*2;
      float b0 = bias[col], b1 = bias[col+1];
      float v0 = acc[im][jn][0] + b0;
      float v1 = acc[im][jn][1] + b1;
      float v2 = acc[im][jn][2] + b0;
      float v3 = acc[im][jn][3] + b1;
      if (ACT){
        v0 = (v0 > 0.f) ? (v0 + 1.f) : __expf(v0);
        v1 = (v1 > 0.f) ? (v1 + 1.f) : __expf(v1);
        v2 = (v2 > 0.f) ? (v2 + 1.f) : __expf(v2);
        v3 = (v3 > 0.f) ? (v3 + 1.f) : __expf(v3);
      }
      float2 o0; o0.x = v0; o0.y = v1;
      float2 o1; o1.x = v2; o1.y = v3;
      if (MODE == 0){
        *(float2*)(out + (size_t)row0*DM + col)     = o0;
        *(float2*)(out + (size_t)(row0+8)*DM + col) = o1;
      } else {
        int hh = col >> 6, dd = col & 63;
        int s0 = row0 >> 2, b_0 = row0 & 3;            // row = s*4 + b
        int s1 = (row0+8) >> 2, b_1 = (row0+8) & 3;
        *(float2*)(out + (((size_t)(b_0*NH + hh))*SEQ + s0)*HD + dd) = o0;
        *(float2*)(out + (((size_t)(b_1*NH + hh))*SEQ + s1)*HD + dd) = o1;
      }
    }
  }
}

// ---------------- KV partial (R1-proven, contiguous [B,H,S,d]) ---------------
__global__ __launch_bounds__(256) void kv_partial(
    const float* __restrict__ Kp, const float* __restrict__ V,
    float* __restrict__ pKV, float* __restrict__ pKs)
{
  const int p  = blockIdx.x;   // b*16+h
  const int ch = blockIdx.y;
  __shared__ float sK[64][64];
  __shared__ float sV[64][64];
  const int tid = threadIdx.x;
  const int ti = tid >> 4, tj = tid & 15;

  float acc[4][4];
  #pragma unroll
  for (int i=0;i<4;i++)
    #pragma unroll
    for (int j=0;j<4;j++) acc[i][j]=0.f;
  float ksum = 0.f;

  const float* Kbase = Kp + ((size_t)p*SEQ + (size_t)ch*RPC)*HD;
  const float* Vbase = V  + ((size_t)p*SEQ + (size_t)ch*RPC)*HD;

  for (int tile = 0; tile < RPC/64; tile++){
    #pragma unroll
    for (int i = 0; i < 4; i++){
      int idx = tid + i*256;   // 1024 float4 = 64x64 floats
      ((float4*)&sK[0][0])[idx] = ((const float4*)(Kbase + (size_t)tile*64*HD))[idx];
      ((float4*)&sV[0][0])[idx] = ((const float4*)(Vbase + (size_t)tile*64*HD))[idx];
    }
    __syncthreads();
    #pragma unroll 4
    for (int s = 0; s < 64; s++){
      float4 a = *(const float4*)&sK[s][ti*4];
      float4 c = *(const float4*)&sV[s][tj*4];
      acc[0][0]+=a.x*c.x; acc[0][1]+=a.x*c.y; acc[0][2]+=a.x*c.z; acc[0][3]+=a.x*c.w;
      acc[1][0]+=a.y*c.x; acc[1][1]+=a.y*c.y; acc[1][2]+=a.y*c.z; acc[1][3]+=a.y*c.w;
      acc[2][0]+=a.z*c.x; acc[2][1]+=a.z*c.y; acc[2][2]+=a.z*c.z; acc[2][3]+=a.z*c.w;
      acc[3][0]+=a.w*c.x; acc[3][1]+=a.w*c.y; acc[3][2]+=a.w*c.z; acc[3][3]+=a.w*c.w;
    }
    if (tid < 64){
      #pragma unroll 8
      for (int s=0;s<64;s++) ksum += sK[s][tid];
    }
    __syncthreads();
  }

  float* dst = pKV + ((size_t)p*NCH + ch)*HD*HD;
  #pragma unroll
  for (int i=0;i<4;i++)
    #pragma unroll
    for (int j=0;j<4;j++)
      dst[(ti*4+i)*HD + tj*4+j] = acc[i][j];
  if (tid < 64) pKs[((size_t)p*NCH + ch)*HD + tid] = ksum;
}

__global__ void kv_reduce(const float* __restrict__ pKV, const float* __restrict__ pKs,
                          float* __restrict__ KV, float* __restrict__ Ks)
{
  const int p = blockIdx.x;
  for (int i = threadIdx.x; i < HD*HD; i += blockDim.x){
    float s = 0.f;
    #pragma unroll
    for (int c = 0; c < NCH; c++) s += pKV[((size_t)p*NCH+c)*HD*HD + i];
    KV[(size_t)p*HD*HD + i] = s;
  }
  if (threadIdx.x < HD){
    float s = 0.f;
    #pragma unroll
    for (int c = 0; c < NCH; c++) s += pKs[((size_t)p*NCH+c)*HD + threadIdx.x];
    Ks[(size_t)p*HD + threadIdx.x] = s;
  }
}

// ---------------- attn = (Qp . KV) / (Qp . Ksum + 1e-6)  (R1-proven) ---------
__global__ __launch_bounds__(256) void attn_apply(
    const float* __restrict__ Qp, const float* __restrict__ KV,
    const float* __restrict__ Ks, float* __restrict__ attn)
{
  const int p  = blockIdx.x;      // b*16+h
  const int st = blockIdx.y;
  __shared__ float sKV[64][64];
  __shared__ float sKs[64];
  const int tid = threadIdx.x, warp = tid >> 5, lane = tid & 31;

  for (int i = tid; i < HD*HD/4; i += 256)
    ((float4*)&sKV[0][0])[i] = ((const float4*)(KV + (size_t)p*HD*HD))[i];
  if (tid < HD) sKs[tid] = Ks[(size_t)p*HD + tid];
  __syncthreads();

  const int b = p >> 4, hh = p & 15;
  for (int r = warp; r < 128; r += 8){
    int s = st*128 + r;
    float2 q2 = *(const float2*)(Qp + ((size_t)p*SEQ + s)*HD + 2*lane);
    float z = q2.x*sKs[2*lane] + q2.y*sKs[2*lane+1];
    #pragma unroll
    for (int off = 16; off; off >>= 1) z += __shfl_xor_sync(0xffffffffu, z, off);
    z += 1e-6f;
    float a0 = 0.f, a1 = 0.f;
    #pragma unroll
    for (int d = 0; d < 64; d++){
      float qd = __shfl_sync(0xffffffffu, (d&1) ? q2.y : q2.x, d>>1);
      float2 kvv = *(const float2*)&sKV[d][2*lane];
      a0 += qd*kvv.x; a1 += qd*kvv.y;
    }
    float inv = 1.0f / z;
    float2 o; o.x = a0*inv; o.y = a1*inv;
    *(float2*)(attn + ((size_t)s*BATCH + b)*DM + hh*HD + 2*lane) = o;
  }
}

// ---------------- host ------------------------------------------------------
extern "C" void kernel_launch(void* const* d_in, const int* in_sizes, int n_in,
                              void* d_out, int out_size)
{
  const float* h  = (const float*)d_in[0];
  const float* x  = (const float*)d_in[1];
  const float* Wq = (const float*)d_in[2];
  const float* bq = (const float*)d_in[3];
  const float* Wk = (const float*)d_in[4];
  const float* bk = (const float*)d_in[5];
  const float* Wv = (const float*)d_in[6];
  const float* bv = (const float*)d_in[7];
  const float* Wo = (const float*)d_in[8];
  const float* bo = (const float*)d_in[9];

  float *qp,*kp,*vv,*attn,*pkv,*pks,*kv,*ks;
  cudaGetSymbolAddress((void**)&qp,   g_Qp);
  cudaGetSymbolAddress((void**)&kp,   g_Kp);
  cudaGetSymbolAddress((void**)&vv,   g_V);
  cudaGetSymbolAddress((void**)&attn, g_attn);
  cudaGetSymbolAddress((void**)&pkv,  g_pKV);
  cudaGetSymbolAddress((void**)&pks,  g_pKs);
  cudaGetSymbolAddress((void**)&kv,   g_KV);
  cudaGetSymbolAddress((void**)&ks,   g_Ks);

  dim3 gg(DM/BN, MTOT/BM);   // 8 x 128
  gemm_ts<1,1><<<gg, 128>>>(h, Wq, bq, qp);
  gemm_ts<1,1><<<gg, 128>>>(x, Wk, bk, kp);
  gemm_ts<1,0><<<gg, 128>>>(x, Wv, bv, vv);

  kv_partial<<<dim3(NPAIR, NCH), 256>>>(kp, vv, pkv, pks);
  kv_reduce<<<NPAIR, 256>>>(pkv, pks, kv, ks);
  attn_apply<<<dim3(NPAIR, SEQ/128), 256>>>(qp, kv, ks, attn);

  gemm_ts<0,0><<<gg, 128>>>(attn, Wo, bo, (float*)d_out);
}